// round 2
// baseline (speedup 1.0000x reference)
#include <cuda_runtime.h>
#include <cuda_bf16.h>

// Fixed problem shapes
#define B    8
#define T    16
#define C    64
#define H    56
#define W_   56
#define HW   (H * W_)          // 3136
#define HW4  (HW / 4)          // 784
#define DIM  8
#define POOL 7                 // H/DIM
#define FEAT (DIM * DIM)       // 64
#define DH   64                // dim_head
#define BC   (B * C)           // 512
#define LN_EPS 1e-5f

// ---------------------------------------------------------------------------
// Fully fused kernel: one CTA per (b,c).
//   Phase A: stream 16 t-slices of x[b,:,c,:,:] through smem, 7x7 mean-pool
//            -> tokens s[16][64]; +pos; LayerNorm; QK projection; 16x16 dots;
//            softmax -> a[16][16] in smem.
//   Phase B: re-read the same slice (L2-hot), out[t] = x[t] + sum_j a[t][j]*x[j]
//            per float4 spatial position, registers only.
// DRAM traffic target: x read once (103 MB, phase-B re-read hits L2) + out
// write once (103 MB) = 206 MB total.
// ---------------------------------------------------------------------------
__global__ __launch_bounds__(256, 2)
void cta_fused_kernel(const float* __restrict__ x,
                      const float* __restrict__ pos,
                      const float* __restrict__ Wqk,
                      const float* __restrict__ gamma,
                      const float* __restrict__ beta,
                      float* __restrict__ out)
{
    const int bc  = blockIdx.x;          // 0..511
    const int b   = bc >> 6;
    const int c   = bc & 63;
    const int tid = threadIdx.x;         // 256 threads

    __shared__ float stage[HW];          // 12544 B : one (b,t,c) spatial slice
    __shared__ float s[T][FEAT];         // 4096 B  : pooled tokens
    __shared__ float qk[T][2 * DH];      // 8192 B  : q | k
    __shared__ float a[T][T];            // 1024 B  : attention weights
    __shared__ float mu[T], rs[T];

    const float4* xb = reinterpret_cast<const float4*>(x);

    const int base    = (b * T * C + c) * HW4;   // float4 index of (b, t=0, c)
    const int tstride = C * HW4;                 // per-t stride in float4

    // ---------------- Phase A: pooling ----------------
    for (int t = 0; t < T; t++) {
        const int tb = base + t * tstride;
        for (int p = tid; p < HW4; p += 256)
            reinterpret_cast<float4*>(stage)[p] = xb[tb + p];
        __syncthreads();

        // 64 cells x 4 threads each: cell = tid>>2, sub = tid&3
        const int cell = tid >> 2;
        const int sub  = tid & 3;
        const int ci   = cell >> 3;
        const int cj   = cell & 7;
        float sum = 0.f;
        for (int e = sub; e < POOL * POOL; e += 4) {
            int i = e / POOL, j = e % POOL;
            sum += stage[(ci * POOL + i) * W_ + cj * POOL + j];
        }
        sum += __shfl_xor_sync(0xffffffffu, sum, 1);
        sum += __shfl_xor_sync(0xffffffffu, sum, 2);
        if (sub == 0) s[t][cell] = sum * (1.f / (POOL * POOL));
        __syncthreads();     // stage reused next t
    }

    // ---------------- + pos_embedding ----------------
    {
        float* sf = &s[0][0];
        const float* pp = pos + bc * (T * FEAT);
        for (int i = tid; i < T * FEAT; i += 256) sf[i] += pp[i];
    }
    __syncthreads();

    // ---------------- LayerNorm ----------------
    if (tid < T) {
        float m = 0.f, v = 0.f;
        #pragma unroll
        for (int f = 0; f < FEAT; f++) { float val = s[tid][f]; m += val; v += val * val; }
        m *= (1.f / FEAT);
        v = v * (1.f / FEAT) - m * m;
        mu[tid] = m;
        rs[tid] = rsqrtf(v + LN_EPS);
    }
    __syncthreads();
    {
        float* sf = &s[0][0];
        for (int i = tid; i < T * FEAT; i += 256) {
            int t = i >> 6, f = i & 63;
            sf[i] = (sf[i] - mu[t]) * rs[t] * gamma[f] + beta[f];
        }
    }
    __syncthreads();

    // ---------------- qk = s @ Wqk : 16x128 outputs, 8 per thread ----------------
    for (int i = tid; i < T * 2 * DH; i += 256) {
        const int t = i >> 7;
        const int o = i & 127;
        float acc = 0.f;
        #pragma unroll
        for (int f = 0; f < FEAT; f++) acc += s[t][f] * __ldg(&Wqk[f * (2 * DH) + o]);
        qk[t][o] = acc;
    }
    __syncthreads();

    // ---------------- dots + softmax: one thread per (i,j) ----------------
    {
        const int i = tid >> 4;
        const int j = tid & 15;
        float d = 0.f;
        #pragma unroll
        for (int k = 0; k < DH; k++) d += qk[i][k] * qk[j][DH + k];
        d *= 0.125f;                       // DH^-0.5

        float mx = d;
        #pragma unroll
        for (int m = 8; m; m >>= 1) mx = fmaxf(mx, __shfl_xor_sync(0xffffffffu, mx, m, 16));
        float e = __expf(d - mx);
        float ss = e;
        #pragma unroll
        for (int m = 8; m; m >>= 1) ss += __shfl_xor_sync(0xffffffffu, ss, m, 16);

        a[i][j] = e / ss;
    }
    __syncthreads();

    // ---------------- Phase B: out[t] = x[t] + sum_j a[t][j] * x[j] ----------------
    // Slice lines are L2-hot from Phase A. __ldcs: last read -> evict-first.
    // __stcs: streaming store, don't thrash other CTAs' slices.
    float4*       ob = reinterpret_cast<float4*>(out);

    for (int p = tid; p < HW4; p += 256) {
        float4 xv[T];
        #pragma unroll
        for (int j = 0; j < T; j++)
            xv[j] = __ldcs(&xb[base + j * tstride + p]);

        #pragma unroll
        for (int t = 0; t < T; t++) {
            float4 acc = xv[t];   // residual
            #pragma unroll
            for (int j = 0; j < T; j++) {
                const float w = a[t][j];
                acc.x = fmaf(w, xv[j].x, acc.x);
                acc.y = fmaf(w, xv[j].y, acc.y);
                acc.z = fmaf(w, xv[j].z, acc.z);
                acc.w = fmaf(w, xv[j].w, acc.w);
            }
            __stcs(&ob[base + t * tstride + p], acc);
        }
    }
}

// ---------------------------------------------------------------------------
extern "C" void kernel_launch(void* const* d_in, const int* in_sizes, int n_in,
                              void* d_out, int out_size)
{
    const float* x     = (const float*)d_in[0];   // (8,16,64,56,56)
    const float* pos   = (const float*)d_in[1];   // (512,16,64)
    const float* Wqk   = (const float*)d_in[2];   // (64,128)
    const float* gamma = (const float*)d_in[3];   // (64,)
    const float* beta  = (const float*)d_in[4];   // (64,)
    float*       out   = (float*)d_out;

    cta_fused_kernel<<<BC, 256>>>(x, pos, Wqk, gamma, beta, out);
}

// round 3
// speedup vs baseline: 1.5502x; 1.5502x over previous
#include <cuda_runtime.h>
#include <cuda_bf16.h>

// Fixed problem shapes
#define B    8
#define T    16
#define C    64
#define H    56
#define W_   56
#define HW   (H * W_)          // 3136
#define HW4  (HW / 4)          // 784
#define DIM  8
#define POOL 7                 // H/DIM
#define FEAT (DIM * DIM)       // 64
#define DH   64                // dim_head
#define BC   (B * C)           // 512
#define BTC  (B * T * C)       // 8192
#define LN_EPS 1e-5f

// Static device scratch (no allocations allowed)
__device__ float g_pool[BC * T * FEAT];   // (bc, t, 64)  = 2 MB
__device__ float g_attn[BC * T * T];      // (bc, 16, 16) = 512 KB

// ---------------------------------------------------------------------------
// K1: one CTA per (b,t,c) slice (8192 blocks). Stage 12.5 KB in smem,
// 7x7 mean-pool -> 64 cells, write to g_pool[(b*C+c)][t][cell].
// Pure 103 MB coalesced stream; leaves x hot in L2 for K3.
// ---------------------------------------------------------------------------
__global__ __launch_bounds__(256, 8)
void pool_kernel(const float* __restrict__ x)
{
    const int slice = blockIdx.x;            // ((b*T + t)*C + c)
    const int c = slice % C;
    const int t = (slice / C) % T;
    const int b = slice / (T * C);
    const int tid = threadIdx.x;

    __shared__ float stage[HW];              // 12544 B

    const float4* xs = reinterpret_cast<const float4*>(x) + (long)slice * HW4;
    #pragma unroll
    for (int p = tid; p < HW4; p += 256)
        reinterpret_cast<float4*>(stage)[p] = xs[p];
    __syncthreads();

    // 64 cells x 4 threads: cell = tid>>2, sub = tid&3
    const int cell = tid >> 2;
    const int sub  = tid & 3;
    const int ci   = cell >> 3;
    const int cj   = cell & 7;
    float sum = 0.f;
    for (int e = sub; e < POOL * POOL; e += 4) {
        int i = e / POOL, j = e % POOL;
        sum += stage[(ci * POOL + i) * W_ + cj * POOL + j];
    }
    sum += __shfl_xor_sync(0xffffffffu, sum, 1);
    sum += __shfl_xor_sync(0xffffffffu, sum, 2);
    if (sub == 0)
        g_pool[((b * C + c) * T + t) * FEAT + cell] = sum * (1.f / (POOL * POOL));
}

// ---------------------------------------------------------------------------
// K2: one CTA per (b,c) (512 blocks). +pos, LayerNorm, QK projection,
// 16x16 dots, softmax -> g_attn. Tiny (4 MB total traffic).
// ---------------------------------------------------------------------------
__global__ __launch_bounds__(256, 4)
void attn_kernel(const float* __restrict__ pos,
                 const float* __restrict__ Wqk,
                 const float* __restrict__ gamma,
                 const float* __restrict__ beta)
{
    const int bc  = blockIdx.x;
    const int tid = threadIdx.x;

    __shared__ float s[T][FEAT];        // 4 KB
    __shared__ float qk[T][2 * DH];     // 8 KB
    __shared__ float mu[T], rs[T];

    // load pooled tokens + pos
    {
        float* sf = &s[0][0];
        const float* gp = g_pool + bc * (T * FEAT);
        const float* pp = pos    + bc * (T * FEAT);
        for (int i = tid; i < T * FEAT; i += 256) sf[i] = gp[i] + pp[i];
    }
    __syncthreads();

    // LayerNorm stats
    if (tid < T) {
        float m = 0.f, v = 0.f;
        #pragma unroll
        for (int f = 0; f < FEAT; f++) { float val = s[tid][f]; m += val; v += val * val; }
        m *= (1.f / FEAT);
        v = v * (1.f / FEAT) - m * m;
        mu[tid] = m;
        rs[tid] = rsqrtf(v + LN_EPS);
    }
    __syncthreads();
    {
        float* sf = &s[0][0];
        for (int i = tid; i < T * FEAT; i += 256) {
            int t = i >> 6, f = i & 63;
            sf[i] = (sf[i] - mu[t]) * rs[t] * gamma[f] + beta[f];
        }
    }
    __syncthreads();

    // qk = s @ Wqk : 16x128 outputs, 8 per thread
    for (int i = tid; i < T * 2 * DH; i += 256) {
        const int t = i >> 7;
        const int o = i & 127;
        float acc = 0.f;
        #pragma unroll
        for (int f = 0; f < FEAT; f++) acc += s[t][f] * __ldg(&Wqk[f * (2 * DH) + o]);
        qk[t][o] = acc;
    }
    __syncthreads();

    // dots + softmax: one thread per (i,j)
    {
        const int i = tid >> 4;
        const int j = tid & 15;
        float d = 0.f;
        #pragma unroll
        for (int k = 0; k < DH; k++) d += qk[i][k] * qk[j][DH + k];
        d *= 0.125f;                        // DH^-0.5

        float mx = d;
        #pragma unroll
        for (int m = 8; m; m >>= 1) mx = fmaxf(mx, __shfl_xor_sync(0xffffffffu, mx, m, 16));
        float e = __expf(d - mx);
        float ss = e;
        #pragma unroll
        for (int m = 8; m; m >>= 1) ss += __shfl_xor_sync(0xffffffffu, ss, m, 16);

        g_attn[bc * (T * T) + i * T + j] = e / ss;
    }
}

// ---------------------------------------------------------------------------
// K3: grid (4, 512): blockIdx.y = (b,c), one float4 spatial position per
// thread. out[t] = x[t] + sum_j a[t][j]*x[j]. x loads hit L2 (warm from K1).
// ---------------------------------------------------------------------------
__global__ __launch_bounds__(256)
void out_kernel(const float* __restrict__ x, float* __restrict__ out)
{
    const int bc = blockIdx.y;
    const int b  = bc >> 6;
    const int c  = bc & 63;

    __shared__ float a[T * T];
    a[threadIdx.x] = g_attn[bc * (T * T) + threadIdx.x];
    __syncthreads();

    const int p = blockIdx.x * 256 + threadIdx.x;
    if (p >= HW4) return;

    const float4* xb = reinterpret_cast<const float4*>(x);
    float4*       ob = reinterpret_cast<float4*>(out);

    const int base    = (b * T * C + c) * HW4;   // t = 0
    const int tstride = C * HW4;                 // per-t stride (float4)

    float4 xv[T];
    #pragma unroll
    for (int j = 0; j < T; j++)
        xv[j] = __ldcs(&xb[base + j * tstride + p]);

    #pragma unroll
    for (int t = 0; t < T; t++) {
        float4 acc = xv[t];   // residual
        #pragma unroll
        for (int j = 0; j < T; j++) {
            const float w = a[t * T + j];
            acc.x = fmaf(w, xv[j].x, acc.x);
            acc.y = fmaf(w, xv[j].y, acc.y);
            acc.z = fmaf(w, xv[j].z, acc.z);
            acc.w = fmaf(w, xv[j].w, acc.w);
        }
        __stcs(&ob[base + t * tstride + p], acc);
    }
}

// ---------------------------------------------------------------------------
extern "C" void kernel_launch(void* const* d_in, const int* in_sizes, int n_in,
                              void* d_out, int out_size)
{
    const float* x     = (const float*)d_in[0];   // (8,16,64,56,56)
    const float* pos   = (const float*)d_in[1];   // (512,16,64)
    const float* Wqk   = (const float*)d_in[2];   // (64,128)
    const float* gamma = (const float*)d_in[3];   // (64,)
    const float* beta  = (const float*)d_in[4];   // (64,)
    float*       out   = (float*)d_out;

    pool_kernel<<<BTC, 256>>>(x);
    attn_kernel<<<BC, 256>>>(pos, Wqk, gamma, beta);
    out_kernel<<<dim3((HW4 + 255) / 256, BC), 256>>>(x, out);
}

// round 5
// speedup vs baseline: 1.7064x; 1.1007x over previous
#include <cuda_runtime.h>
#include <cuda_bf16.h>

// Fixed problem shapes
#define B    8
#define T    16
#define C    64
#define H    56
#define W_   56
#define HW   (H * W_)          // 3136
#define HW4  (HW / 4)          // 784
#define DIM  8
#define POOL 7                 // H/DIM
#define FEAT (DIM * DIM)       // 64
#define DH   64                // dim_head
#define BC   (B * C)           // 512
#define BTC  (B * T * C)       // 8192
#define LN_EPS 1e-5f

// Static device scratch (no allocations allowed)
__device__ float g_pool[BC * T * FEAT];   // (bc, t, 64)  = 2 MB
__device__ float g_attn[BC * T * T];      // (bc, 16, 16) = 512 KB

// Packed f32x2 FMA (Blackwell): d = a*b + c on 2 floats per instruction.
__device__ __forceinline__ unsigned long long ffma2(unsigned long long a,
                                                    unsigned long long b,
                                                    unsigned long long c)
{
    unsigned long long d;
    asm("fma.rn.f32x2 %0, %1, %2, %3;" : "=l"(d) : "l"(a), "l"(b), "l"(c));
    return d;
}

union F4U { float4 f; unsigned long long u[2]; };

// ---------------------------------------------------------------------------
// K1: one CTA per (b,t,c) slice (8192 blocks). Stage 12.5 KB in smem,
// 7x7 mean-pool -> 64 cells. All reduce offsets compile-time (no div/mod).
// ---------------------------------------------------------------------------
__global__ __launch_bounds__(256, 8)
void pool_kernel(const float* __restrict__ x)
{
    const int slice = blockIdx.x;            // ((b*T + t)*C + c)
    const int c = slice % C;
    const int t = (slice / C) % T;
    const int b = slice / (T * C);
    const int tid = threadIdx.x;

    __shared__ float stage[HW];              // 12544 B

    const float4* xs = reinterpret_cast<const float4*>(x) + (long)slice * HW4;
    float4* st4 = reinterpret_cast<float4*>(stage);
    // 784 = 3*256 + 16
    st4[tid]        = xs[tid];
    st4[tid + 256]  = xs[tid + 256];
    st4[tid + 512]  = xs[tid + 512];
    if (tid < 16) st4[tid + 768] = xs[tid + 768];
    __syncthreads();

    // 64 cells x 4 subs. sub handles rows {sub, sub+4} (sub==3: one row).
    const int cell = tid >> 2;
    const int sub  = tid & 3;
    const int ci   = cell >> 3;
    const int cj   = cell & 7;

    const float* r0 = stage + (ci * POOL + sub) * W_ + cj * POOL;
    float sum = 0.f;
    #pragma unroll
    for (int jj = 0; jj < POOL; jj++) sum += r0[jj];
    if (sub < 3) {
        #pragma unroll
        for (int jj = 0; jj < POOL; jj++) sum += r0[4 * W_ + jj];
    }
    sum += __shfl_xor_sync(0xffffffffu, sum, 1);
    sum += __shfl_xor_sync(0xffffffffu, sum, 2);
    if (sub == 0)
        g_pool[((b * C + c) * T + t) * FEAT + cell] = sum * (1.f / (POOL * POOL));
}

// ---------------------------------------------------------------------------
// K2: one CTA per (b,c) (512 blocks). +pos, LayerNorm, QK projection,
// 16x16 dots, softmax -> g_attn. Tiny.
// ---------------------------------------------------------------------------
__global__ __launch_bounds__(256, 4)
void attn_kernel(const float* __restrict__ pos,
                 const float* __restrict__ Wqk,
                 const float* __restrict__ gamma,
                 const float* __restrict__ beta)
{
    const int bc  = blockIdx.x;
    const int tid = threadIdx.x;

    __shared__ float s[T][FEAT];        // 4 KB
    __shared__ float qk[T][2 * DH];     // 8 KB
    __shared__ float mu[T], rs[T];

    {
        float* sf = &s[0][0];
        const float* gp = g_pool + bc * (T * FEAT);
        const float* pp = pos    + bc * (T * FEAT);
        for (int i = tid; i < T * FEAT; i += 256) sf[i] = gp[i] + pp[i];
    }
    __syncthreads();

    if (tid < T) {
        float m = 0.f, v = 0.f;
        #pragma unroll
        for (int f = 0; f < FEAT; f++) { float val = s[tid][f]; m += val; v += val * val; }
        m *= (1.f / FEAT);
        v = v * (1.f / FEAT) - m * m;
        mu[tid] = m;
        rs[tid] = rsqrtf(v + LN_EPS);
    }
    __syncthreads();
    {
        float* sf = &s[0][0];
        for (int i = tid; i < T * FEAT; i += 256) {
            int t = i >> 6, f = i & 63;
            sf[i] = (sf[i] - mu[t]) * rs[t] * gamma[f] + beta[f];
        }
    }
    __syncthreads();

    for (int i = tid; i < T * 2 * DH; i += 256) {
        const int t = i >> 7;
        const int o = i & 127;
        float acc = 0.f;
        #pragma unroll
        for (int f = 0; f < FEAT; f++) acc += s[t][f] * __ldg(&Wqk[f * (2 * DH) + o]);
        qk[t][o] = acc;
    }
    __syncthreads();

    {
        const int i = tid >> 4;
        const int j = tid & 15;
        float d = 0.f;
        #pragma unroll
        for (int k = 0; k < DH; k++) d += qk[i][k] * qk[j][DH + k];
        d *= 0.125f;                        // DH^-0.5

        float mx = d;
        #pragma unroll
        for (int m = 8; m; m >>= 1) mx = fmaxf(mx, __shfl_xor_sync(0xffffffffu, mx, m, 16));
        float e = __expf(d - mx);
        float ss = e;
        #pragma unroll
        for (int m = 8; m; m >>= 1) ss += __shfl_xor_sync(0xffffffffu, ss, m, 16);

        g_attn[bc * (T * T) + i * T + j] = e / ss;
    }
}

// ---------------------------------------------------------------------------
// K3: grid (4, 512): blockIdx.y = (b,c), one float4 spatial position per
// thread. out[t] = x[t] + sum_j a[t][j]*x[j] via packed f32x2 FMAs.
// Attention weights pre-packed in smem as {w,w} f32x2 pairs: inner loop is
// one LDS.64 + 2 FFMA2 per j. x loads hit L2 (warm from K1); streaming stores.
// ---------------------------------------------------------------------------
__global__ __launch_bounds__(256)
void out_kernel(const float* __restrict__ x, float* __restrict__ out)
{
    const int bc = blockIdx.y;
    const int b  = bc >> 6;
    const int c  = bc & 63;

    __shared__ unsigned long long a2[T * T];   // packed {w,w}, 2 KB
    {
        const float w = g_attn[bc * (T * T) + threadIdx.x];
        unsigned long long wp;
        asm("mov.b64 %0, {%1, %1};" : "=l"(wp) : "f"(w));
        a2[threadIdx.x] = wp;
    }
    __syncthreads();

    const int p = blockIdx.x * 256 + threadIdx.x;
    if (p >= HW4) return;

    const float4* xb = reinterpret_cast<const float4*>(x);
    float4*       ob = reinterpret_cast<float4*>(out);

    const int base    = (b * T * C + c) * HW4;   // t = 0
    const int tstride = C * HW4;                 // per-t stride (float4)

    // Load 16 float4 as 32 packed f32x2 values
    unsigned long long xv[T][2];
    #pragma unroll
    for (int j = 0; j < T; j++) {
        F4U v; v.f = __ldcs(&xb[base + j * tstride + p]);
        xv[j][0] = v.u[0];
        xv[j][1] = v.u[1];
    }

    #pragma unroll
    for (int t = 0; t < T; t++) {
        unsigned long long acc0 = xv[t][0];   // residual
        unsigned long long acc1 = xv[t][1];
        #pragma unroll
        for (int j = 0; j < T; j++) {
            const unsigned long long wp = a2[t * T + j];
            acc0 = ffma2(wp, xv[j][0], acc0);
            acc1 = ffma2(wp, xv[j][1], acc1);
        }
        F4U r; r.u[0] = acc0; r.u[1] = acc1;
        __stcs(&ob[base + t * tstride + p], r.f);
    }
}

// ---------------------------------------------------------------------------
extern "C" void kernel_launch(void* const* d_in, const int* in_sizes, int n_in,
                              void* d_out, int out_size)
{
    const float* x     = (const float*)d_in[0];   // (8,16,64,56,56)
    const float* pos   = (const float*)d_in[1];   // (512,16,64)
    const float* Wqk   = (const float*)d_in[2];   // (64,128)
    const float* gamma = (const float*)d_in[3];   // (64,)
    const float* beta  = (const float*)d_in[4];   // (64,)
    float*       out   = (float*)d_out;

    pool_kernel<<<BTC, 256>>>(x);
    attn_kernel<<<BC, 256>>>(pos, Wqk, gamma, beta);
    out_kernel<<<dim3((HW4 + 255) / 256, BC), 256>>>(x, out);
}